// round 1
// baseline (speedup 1.0000x reference)
#include <cuda_runtime.h>

#define B_      64
#define SSTATE  512
#define SSEQ    2048
#define HDIM    512

// Scratch (static device globals — no runtime allocation).
__device__ float g_Q[(size_t)B_ * SSTATE * HDIM];   // 64 MiB: Q = out_state @ W
__device__ float g_c[B_ * SSTATE];                  // c[b,i] = out_state[b,i,:] . bias

// ---------------------------------------------------------------------------
// K1: Q[m, d] = sum_h S[m, h] * W[h, d]   (m = b*512+i flattened, M=32768)
// CTA tile 128x64, K-chunk 32, 256 threads, 8x4 register microtile.
// As stored [k][m] with XOR-swizzled 16B groups (conflict-free STS scatter +
// aligned LDS.128). Bs natural [k][n].
// ---------------------------------------------------------------------------
__global__ __launch_bounds__(256, 2)
void gemm_qs_kernel(const float* __restrict__ A, const float* __restrict__ Bw) {
    __shared__ float As[32][128];
    __shared__ float Bs[32][64];
    const int K = HDIM;
    int tid = threadIdx.x;
    int m0 = blockIdx.y * 128;
    int n0 = blockIdx.x * 64;
    int tx = tid & 15, ty = tid >> 4;

    float acc[8][4];
#pragma unroll
    for (int r = 0; r < 8; r++)
#pragma unroll
        for (int c = 0; c < 4; c++) acc[r][c] = 0.f;

    for (int k0 = 0; k0 < K; k0 += 32) {
        __syncthreads();
        // A tile: 128 rows x 32 k. Each thread: 4x float4 along k (coalesced),
        // scatter-store transposed into As[k][swizzled m].
#pragma unroll
        for (int q = 0; q < 4; q++) {
            int idx = tid + 256 * q;
            int m = idx >> 3, kq = idx & 7;
            float4 v = *(const float4*)(A + (size_t)(m0 + m) * K + k0 + (kq << 2));
            int col = ((((m >> 2) ^ kq) << 2) | (m & 3));
            As[(kq << 2) + 0][col] = v.x;
            As[(kq << 2) + 1][col] = v.y;
            As[(kq << 2) + 2][col] = v.z;
            As[(kq << 2) + 3][col] = v.w;
        }
        // B tile: 32 k-rows x 64 n, natural layout (rows of W are n-contiguous).
#pragma unroll
        for (int q = 0; q < 2; q++) {
            int idx = tid + 256 * q;
            int kk = idx >> 4, nq = idx & 15;
            *(float4*)&Bs[kk][nq << 2] =
                *(const float4*)(Bw + (size_t)(k0 + kk) * HDIM + n0 + (nq << 2));
        }
        __syncthreads();
#pragma unroll
        for (int k = 0; k < 32; k++) {
            int sw = k >> 2;
            float4 a0 = *(const float4*)&As[k][(ty ^ sw) << 2];
            float4 a1 = *(const float4*)&As[k][((16 + ty) ^ sw) << 2];
            float4 bv = *(const float4*)&Bs[k][tx << 2];
            float av[8] = {a0.x, a0.y, a0.z, a0.w, a1.x, a1.y, a1.z, a1.w};
            float bw[4] = {bv.x, bv.y, bv.z, bv.w};
#pragma unroll
            for (int r = 0; r < 8; r++)
#pragma unroll
                for (int c = 0; c < 4; c++)
                    acc[r][c] = fmaf(av[r], bw[c], acc[r][c]);
        }
    }
#pragma unroll
    for (int r = 0; r < 8; r++) {
        int m = ((r & 4) << 4) + (ty << 2) + (r & 3);  // rows ty*4+r and 64+ty*4+(r-4)
        *(float4*)&g_Q[(size_t)(m0 + m) * HDIM + n0 + (tx << 2)] =
            make_float4(acc[r][0], acc[r][1], acc[r][2], acc[r][3]);
    }
}

// ---------------------------------------------------------------------------
// bias dot: c[row] = S[row,:] . bias   (one warp per row)
// ---------------------------------------------------------------------------
__global__ __launch_bounds__(256)
void bias_dot_kernel(const float* __restrict__ S, const float* __restrict__ bias) {
    int warp = threadIdx.x >> 5, lane = threadIdx.x & 31;
    int row = blockIdx.x * 8 + warp;
    const float4* sp = (const float4*)(S + (size_t)row * HDIM);
    const float4* bp = (const float4*)bias;
    float acc = 0.f;
#pragma unroll
    for (int q = 0; q < 4; q++) {
        float4 s = sp[lane + (q << 5)];
        float4 b = bp[lane + (q << 5)];
        acc = fmaf(s.x, b.x, fmaf(s.y, b.y, fmaf(s.z, b.z, fmaf(s.w, b.w, acc))));
    }
#pragma unroll
    for (int off = 16; off; off >>= 1) acc += __shfl_xor_sync(0xffffffffu, acc, off);
    if (lane == 0) g_c[row] = acc;
}

// ---------------------------------------------------------------------------
// K2: E[b, i, j] = sum_d Q[b,i,d] * hist[b,j,d] + c[b,i]   (NT GEMM, batched)
// Same microkernel; B tile is k-contiguous like A (history rows), so it gets
// the same transposed+swizzled store. Raw energies written to d_out.
// Grid: (j-tiles=32, i-tiles=4, b=64) -> per-batch working set ~5MB stays in L2.
// ---------------------------------------------------------------------------
__global__ __launch_bounds__(256, 2)
void gemm_energy_kernel(const float* __restrict__ Hst, float* __restrict__ out) {
    __shared__ float As[32][128];
    __shared__ float Bs[32][64];
    const int K = HDIM;
    int bb = blockIdx.z;
    const float* A  = g_Q + (size_t)bb * SSTATE * HDIM;
    const float* Bh = Hst + (size_t)bb * SSEQ * HDIM;
    float* C = out + (size_t)bb * SSTATE * SSEQ;
    int tid = threadIdx.x;
    int m0 = blockIdx.y * 128;   // i
    int n0 = blockIdx.x * 64;    // j
    int tx = tid & 15, ty = tid >> 4;

    float acc[8][4];
#pragma unroll
    for (int r = 0; r < 8; r++)
#pragma unroll
        for (int c = 0; c < 4; c++) acc[r][c] = 0.f;

    for (int k0 = 0; k0 < K; k0 += 32) {
        __syncthreads();
#pragma unroll
        for (int q = 0; q < 4; q++) {
            int idx = tid + 256 * q;
            int m = idx >> 3, kq = idx & 7;
            float4 v = *(const float4*)(A + (size_t)(m0 + m) * K + k0 + (kq << 2));
            int col = ((((m >> 2) ^ kq) << 2) | (m & 3));
            As[(kq << 2) + 0][col] = v.x;
            As[(kq << 2) + 1][col] = v.y;
            As[(kq << 2) + 2][col] = v.z;
            As[(kq << 2) + 3][col] = v.w;
        }
#pragma unroll
        for (int q = 0; q < 2; q++) {
            int idx = tid + 256 * q;
            int j = idx >> 3, kq = idx & 7;
            float4 v = *(const float4*)(Bh + (size_t)(n0 + j) * HDIM + k0 + (kq << 2));
            int col = ((((j >> 2) ^ kq) << 2) | (j & 3));
            Bs[(kq << 2) + 0][col] = v.x;
            Bs[(kq << 2) + 1][col] = v.y;
            Bs[(kq << 2) + 2][col] = v.z;
            Bs[(kq << 2) + 3][col] = v.w;
        }
        __syncthreads();
#pragma unroll
        for (int k = 0; k < 32; k++) {
            int sw = k >> 2;
            float4 a0 = *(const float4*)&As[k][(ty ^ sw) << 2];
            float4 a1 = *(const float4*)&As[k][((16 + ty) ^ sw) << 2];
            float4 bv = *(const float4*)&Bs[k][(tx ^ sw) << 2];
            float av[8] = {a0.x, a0.y, a0.z, a0.w, a1.x, a1.y, a1.z, a1.w};
            float bw[4] = {bv.x, bv.y, bv.z, bv.w};
#pragma unroll
            for (int r = 0; r < 8; r++)
#pragma unroll
                for (int c = 0; c < 4; c++)
                    acc[r][c] = fmaf(av[r], bw[c], acc[r][c]);
        }
    }
#pragma unroll
    for (int r = 0; r < 8; r++) {
        int m = ((r & 4) << 4) + (ty << 2) + (r & 3);
        float cv = g_c[bb * SSTATE + m0 + m];
        *(float4*)&C[(size_t)(m0 + m) * SSEQ + n0 + (tx << 2)] =
            make_float4(acc[r][0] + cv, acc[r][1] + cv, acc[r][2] + cv, acc[r][3] + cv);
    }
}

// ---------------------------------------------------------------------------
// K3: in-place softmax over rows of 2048. One CTA (256 thr) per row, values
// held in registers (8/thread). exp via FFMA polynomial (MUFU.EX2 at rt=8
// would cost ~0.5 ms for 67M elements; this costs ~35 us).
// ---------------------------------------------------------------------------
__device__ __forceinline__ float fexp_neg(float x) {   // x <= 0
    float t = x * 1.4426950408889634f;
    t = fmaxf(t, -250.0f);
    float fi = t + 12582912.0f;                 // round-to-nearest-int trick
    int i = __float_as_int(fi) - 0x4B400000;
    float f = t - (fi - 12582912.0f);           // f in [-0.5, 0.5]
    float p = 1.5404e-4f;                       // 2^f Taylor, rel err ~6e-7
    p = fmaf(p, f, 1.33336e-3f);
    p = fmaf(p, f, 9.61813e-3f);
    p = fmaf(p, f, 5.55041e-2f);
    p = fmaf(p, f, 2.40226513e-1f);
    p = fmaf(p, f, 6.93147182e-1f);
    p = fmaf(p, f, 1.0f);
    int i1 = i >> 1;
    int i2 = i - i1;                            // two-step scale handles i < -126
    float s1 = __int_as_float((i1 + 127) << 23);
    float s2 = __int_as_float((i2 + 127) << 23);
    return p * s1 * s2;
}

__global__ __launch_bounds__(256)
void softmax_kernel(float* __restrict__ data) {
    __shared__ float red[8];
    size_t row = blockIdx.x;
    float4* p = (float4*)(data + row * SSEQ);
    int tid = threadIdx.x;
    int lane = tid & 31, warp = tid >> 5;

    float4 v0 = p[tid];
    float4 v1 = p[tid + 256];
    float m = fmaxf(fmaxf(fmaxf(v0.x, v0.y), fmaxf(v0.z, v0.w)),
                    fmaxf(fmaxf(v1.x, v1.y), fmaxf(v1.z, v1.w)));
#pragma unroll
    for (int off = 16; off; off >>= 1) m = fmaxf(m, __shfl_xor_sync(0xffffffffu, m, off));
    if (lane == 0) red[warp] = m;
    __syncthreads();
    float gm = red[0];
#pragma unroll
    for (int w = 1; w < 8; w++) gm = fmaxf(gm, red[w]);
    __syncthreads();

    float e[8];
    e[0] = fexp_neg(v0.x - gm); e[1] = fexp_neg(v0.y - gm);
    e[2] = fexp_neg(v0.z - gm); e[3] = fexp_neg(v0.w - gm);
    e[4] = fexp_neg(v1.x - gm); e[5] = fexp_neg(v1.y - gm);
    e[6] = fexp_neg(v1.z - gm); e[7] = fexp_neg(v1.w - gm);
    float s = ((e[0] + e[1]) + (e[2] + e[3])) + ((e[4] + e[5]) + (e[6] + e[7]));
#pragma unroll
    for (int off = 16; off; off >>= 1) s += __shfl_xor_sync(0xffffffffu, s, off);
    if (lane == 0) red[warp] = s;
    __syncthreads();
    float gs = ((red[0] + red[1]) + (red[2] + red[3])) +
               ((red[4] + red[5]) + (red[6] + red[7]));
    float inv = 1.0f / gs;

    p[tid]       = make_float4(e[0] * inv, e[1] * inv, e[2] * inv, e[3] * inv);
    p[tid + 256] = make_float4(e[4] * inv, e[5] * inv, e[6] * inv, e[7] * inv);
}

// ---------------------------------------------------------------------------
extern "C" void kernel_launch(void* const* d_in, const int* in_sizes, int n_in,
                              void* d_out, int out_size) {
    (void)in_sizes; (void)n_in; (void)out_size;
    const float* S    = (const float*)d_in[0];  // out_state [64,512,512]
    const float* Hst  = (const float*)d_in[1];  // history   [64,2048,512]
    const float* W    = (const float*)d_in[2];  // attn_w    [512,512]
    const float* bias = (const float*)d_in[3];  // attn_b    [512]
    float* out = (float*)d_out;                 // [64,512,2048]

    dim3 g1(HDIM / 64, (B_ * SSTATE) / 128);            // (8, 256)
    gemm_qs_kernel<<<g1, 256>>>(S, W);
    bias_dot_kernel<<<(B_ * SSTATE) / 8, 256>>>(S, bias);
    dim3 g2(SSEQ / 64, SSTATE / 128, B_);               // (32, 4, 64)
    gemm_energy_kernel<<<g2, 256>>>(Hst, out);
    softmax_kernel<<<B_ * SSTATE, 256>>>(out);
}

// round 8
// speedup vs baseline: 3.5076x; 3.5076x over previous
#include <cuda_runtime.h>
#include <cuda_bf16.h>
#include <cstdint>

#define B_      64
#define SSTATE  512
#define SSEQ    2048
#define HDIM    512
#define MTOT    (B_*SSTATE)

// tcgen05 is arch-specific: present only in the sm_103a/sm_100a compilation
// pass. The harness also compiles a plain compute_103 PTX pass where these
// instructions are illegal -> gate the bodies on the arch-feature macros.
#if defined(__CUDA_ARCH_FEAT_SM103_ALL) || defined(__CUDA_ARCH_FEAT_SM100_ALL) || defined(__CUDA_ARCH_SPECIFIC__)
#define TCGEN05_OK 1
#else
#define TCGEN05_OK 0
#endif

// idesc for kind::f16 bf16 x bf16 -> fp32, M=128, N=256 (preprocessor constant:
// must NOT be a gated __device__ variable — the host registration stub would
// reference it in passes where the gate is off).
#define IDESC_128x256 \
    ((1u << 4) | (1u << 7) | (1u << 10) | ((256u / 8) << 17) | ((128u / 16) << 24))

// bf16 hi/lo split scratch (static device globals — no runtime allocation)
__device__ __nv_bfloat16 g_Qhi[(size_t)MTOT * HDIM];   // 32 MiB
__device__ __nv_bfloat16 g_Qlo[(size_t)MTOT * HDIM];   // 32 MiB
__device__ __nv_bfloat16 g_Wth[HDIM * HDIM];           // W^T hi
__device__ __nv_bfloat16 g_Wtl[HDIM * HDIM];           // W^T lo

#if TCGEN05_OK
// ---------------- PTX helpers (sm_103a tcgen05) ----------------
__device__ __forceinline__ uint32_t smem_u32(const void* p) {
    uint32_t a;
    asm("{ .reg .u64 t; cvta.to.shared.u64 t, %1; cvt.u32.u64 %0, t; }" : "=r"(a) : "l"(p));
    return a;
}
__device__ __forceinline__ uint32_t elect_one() {
    uint32_t p;
    asm volatile("{ .reg .pred p; elect.sync _|p, 0xFFFFFFFF; selp.b32 %0,1,0,p; }" : "=r"(p));
    return p;
}
__device__ __forceinline__ uint64_t make_desc(uint32_t addr) {
    // SW128, Blackwell version=1, LBO=1, SBO=64 (K-major 128B rows)
    const uint64_t base = (uint64_t(2) << 61) | (uint64_t(1) << 46) |
                          (uint64_t(64) << 32) | (uint64_t(1) << 16);
    return base | ((uint64_t)(addr >> 4) & 0x3FFF);
}
__device__ __forceinline__ void mma_ss_f16(uint32_t d, uint64_t a, uint64_t b,
                                           uint32_t idesc, uint32_t en) {
    asm volatile(
        "{\n\t.reg .pred p;\n\tsetp.ne.u32 p, %4, 0;\n\t"
        "tcgen05.mma.cta_group::1.kind::f16 [%0], %1, %2, %3, {%5,%5,%5,%5}, p;\n\t}"
        :: "r"(d), "l"(a), "l"(b), "r"(idesc), "r"(en), "r"(0u) : "memory");
}

#define MBAR_INIT(addr, cnt) \
    asm volatile("mbarrier.init.shared.b64 [%0], %1;" :: "r"(addr), "r"(cnt) : "memory")
#define MBAR_WAIT(addr, phv) do {                                                   \
    uint32_t _m = (addr), _p = (uint32_t)(phv), _d;                                 \
    asm volatile("{\n\t.reg .pred p;\n\t"                                           \
        "mbarrier.try_wait.parity.acquire.cta.shared::cta.b64 p, [%1], %2;\n\t"     \
        "selp.b32 %0,1,0,p;\n\t}" : "=r"(_d) : "r"(_m), "r"(_p) : "memory");        \
    if (!_d) {                                                                      \
        asm volatile("{\n\t.reg .pred P1;\n\t"                                      \
        "WL_%=:\n\t"                                                                \
        "mbarrier.try_wait.parity.acquire.cta.shared::cta.b64 P1, [%0], %1, 0x989680;\n\t" \
        "@P1 bra.uni WD_%=;\n\t"                                                    \
        "bra.uni WL_%=;\n\t"                                                        \
        "WD_%=:\n\t}" :: "r"(_m), "r"(_p) : "memory");                              \
    } } while (0)

#define LD32X32(r, ta)                                                              \
    asm volatile("tcgen05.ld.sync.aligned.32x32b.x32.b32 "                          \
        "{%0, %1, %2, %3, %4, %5, %6, %7, %8, %9, %10, %11, %12, %13, %14, %15, "   \
        " %16, %17, %18, %19, %20, %21, %22, %23, %24, %25, %26, %27, %28, %29, %30, %31}, [%32];" \
        : "=r"((r)[0]),"=r"((r)[1]),"=r"((r)[2]),"=r"((r)[3]),                      \
          "=r"((r)[4]),"=r"((r)[5]),"=r"((r)[6]),"=r"((r)[7]),                      \
          "=r"((r)[8]),"=r"((r)[9]),"=r"((r)[10]),"=r"((r)[11]),                    \
          "=r"((r)[12]),"=r"((r)[13]),"=r"((r)[14]),"=r"((r)[15]),                  \
          "=r"((r)[16]),"=r"((r)[17]),"=r"((r)[18]),"=r"((r)[19]),                  \
          "=r"((r)[20]),"=r"((r)[21]),"=r"((r)[22]),"=r"((r)[23]),                  \
          "=r"((r)[24]),"=r"((r)[25]),"=r"((r)[26]),"=r"((r)[27]),                  \
          "=r"((r)[28]),"=r"((r)[29]),"=r"((r)[30]),"=r"((r)[31])                   \
        : "r"(ta))

#define SWZ(o) ((o) ^ (((o) >> 3) & 0x70))
#endif  // TCGEN05_OK

// smem layout (dynamic): [0,8) mbar0, [8,16) mbar1, [16,20) tmem ptr,
// data tiles start at 1024-aligned db; per stage: Ahi 16K | Alo 16K | Bhi 32K | Blo 32K
#define STG_BYTES   98304
#define A_LO_OFF    16384
#define B_HI_OFF    32768
#define B_LO_OFF    65536
#define SMEM_DYN    (2048 + 2*STG_BYTES)   // slack for 1024-alignment

// ---------------------------------------------------------------------------
// W transpose + bf16 split: Wt_hi/lo[d][h] = split(W[h][d])
// ---------------------------------------------------------------------------
__global__ __launch_bounds__(256)
void wt_kernel(const float* __restrict__ W) {
    __shared__ float t[32][33];
    int h0 = blockIdx.y * 32, d0 = blockIdx.x * 32;
    int x = threadIdx.x & 31, y = threadIdx.x >> 5;   // y in 0..7
#pragma unroll
    for (int i = 0; i < 32; i += 8)
        t[y + i][x] = W[(size_t)(h0 + y + i) * HDIM + d0 + x];
    __syncthreads();
#pragma unroll
    for (int i = 0; i < 32; i += 8) {
        float v = t[x][y + i];
        __nv_bfloat16 hi = __float2bfloat16(v);
        __nv_bfloat16 lo = __float2bfloat16(v - __bfloat162float(hi));
        size_t off = (size_t)(d0 + y + i) * HDIM + h0 + x;
        g_Wth[off] = hi;
        g_Wtl[off] = lo;
    }
}

// ---------------------------------------------------------------------------
// K1: Q = S @ W  via tcgen05 bf16x3.  Tile 128(m) x 256(d), K chunks of 64(h).
// A = S fp32 (split on the fly), B = Wt hi/lo.  Epilogue: Q -> bf16 hi/lo.
// ---------------------------------------------------------------------------
__global__ __launch_bounds__(256, 1)
void k1_kernel(const float* __restrict__ S) {
#if TCGEN05_OK
    extern __shared__ char sm[];
    uint32_t sb = smem_u32(sm);
    uint32_t db = (sb + 32 + 1023) & ~1023u;      // 1024-aligned tile base
    char* dp = sm + (db - sb);
    int tid = threadIdx.x, wid = tid >> 5, lane = tid & 31;
    int m0 = blockIdx.y * 128, n0 = blockIdx.x * 256;

    if (wid == 0)
        asm volatile("tcgen05.alloc.cta_group::1.sync.aligned.shared::cta.b32 [%0], %1;"
                     :: "r"(sb + 16), "r"(256u) : "memory");
    if (tid == 0) { MBAR_INIT(sb + 0, 1u); MBAR_INIT(sb + 8, 1u); }
    __syncthreads();
    uint32_t td;
    asm volatile("ld.shared.b32 %0, [%1];" : "=r"(td) : "r"(sb + 16));

    int ph0 = 0, ph1 = 0;
    for (int c = 0; c < 8; c++) {
        int buf = c & 1;
        int k0 = c * 64;
        if (c >= 2) {
            if (buf == 0) { MBAR_WAIT(sb + 0, ph0); ph0 ^= 1; }
            else          { MBAR_WAIT(sb + 8, ph1); ph1 ^= 1; }
        }
        char* st = dp + buf * STG_BYTES;
        // A: S fp32 -> hi/lo.  128 rows x 8 groups(8 floats) = 1024 items.
#pragma unroll
        for (int t = 0; t < 4; t++) {
            int it = tid + 256 * t;
            int r = it >> 3, g = it & 7;
            const float4* s = (const float4*)(S + (size_t)(m0 + r) * HDIM + k0 + g * 8);
            float4 x0 = s[0], x1 = s[1];
            float xs[8] = {x0.x, x0.y, x0.z, x0.w, x1.x, x1.y, x1.z, x1.w};
            union { __nv_bfloat16 b[8]; uint4 u; } Hh, Ll;
#pragma unroll
            for (int e = 0; e < 8; e++) {
                __nv_bfloat16 h = __float2bfloat16(xs[e]);
                Hh.b[e] = h;
                Ll.b[e] = __float2bfloat16(xs[e] - __bfloat162float(h));
            }
            int o = SWZ(r * 128 + g * 16);
            *(uint4*)(st + o)            = Hh.u;
            *(uint4*)(st + A_LO_OFF + o) = Ll.u;
        }
        // B: Wt hi/lo bf16.  256 rows x 8 groups(16B) = 2048 items per matrix.
#pragma unroll
        for (int t = 0; t < 8; t++) {
            int it = tid + 256 * t;
            int r = it >> 3, g = it & 7;
            int o = SWZ(r * 128 + g * 16);
            size_t src = (size_t)(n0 + r) * HDIM + k0 + g * 8;
            *(uint4*)(st + B_HI_OFF + o) = *(const uint4*)(g_Wth + src);
            *(uint4*)(st + B_LO_OFF + o) = *(const uint4*)(g_Wtl + src);
        }
        asm volatile("fence.proxy.async.shared::cta;" ::: "memory");
        __syncthreads();
        if (wid == 0 && elect_one()) {
            uint32_t ba = db + buf * STG_BYTES;
            uint64_t ah = make_desc(ba), al = make_desc(ba + A_LO_OFF);
            uint64_t bh = make_desc(ba + B_HI_OFF), bl = make_desc(ba + B_LO_OFF);
#pragma unroll
            for (int ks = 0; ks < 4; ks++)
                mma_ss_f16(td, ah + 2 * ks, bh + 2 * ks, IDESC_128x256,
                           (c == 0 && ks == 0) ? 0u : 1u);
#pragma unroll
            for (int ks = 0; ks < 4; ks++)
                mma_ss_f16(td, ah + 2 * ks, bl + 2 * ks, IDESC_128x256, 1u);
#pragma unroll
            for (int ks = 0; ks < 4; ks++)
                mma_ss_f16(td, al + 2 * ks, bh + 2 * ks, IDESC_128x256, 1u);
            asm volatile(
                "tcgen05.commit.cta_group::1.mbarrier::arrive::one.shared::cluster.b64 [%0];"
                :: "r"(sb + buf * 8) : "memory");
        }
    }
    MBAR_WAIT(sb + 8, ph1);   // chunk 7 (buf 1) completion => all MMA done (in-order pipe)
    asm volatile("tcgen05.fence::after_thread_sync;" ::: "memory");

    // Epilogue: D fp32 [128 x 256] in TMEM cols 0..255.
    // warp w: rows (w&3)*32+lane, col block (w>>2)*128, 4 iters of 32 cols.
    int mrow = m0 + ((wid & 3) << 5) + lane;
    int cb = (wid >> 2) * 128;
#pragma unroll
    for (int itn = 0; itn < 4; itn++) {
        uint32_t dr[32];
        LD32X32(dr, td + cb + itn * 32);
        asm volatile("tcgen05.wait::ld.sync.aligned;" ::: "memory");
#pragma unroll
        for (int g = 0; g < 4; g++) {
            union { __nv_bfloat16 b[8]; uint4 u; } Hh, Ll;
#pragma unroll
            for (int e = 0; e < 8; e++) {
                float q = __uint_as_float(dr[g * 8 + e]);
                __nv_bfloat16 h = __float2bfloat16(q);
                Hh.b[e] = h;
                Ll.b[e] = __float2bfloat16(q - __bfloat162float(h));
            }
            size_t off = (size_t)mrow * HDIM + n0 + cb + itn * 32 + g * 8;
            *(uint4*)(g_Qhi + off) = Hh.u;
            *(uint4*)(g_Qlo + off) = Ll.u;
        }
    }
    __syncthreads();
    if (wid == 0)
        asm volatile("tcgen05.dealloc.cta_group::1.sync.aligned.b32 %0, %1;"
                     :: "r"(td), "r"(256u));
#endif  // TCGEN05_OK
}

// ---------------------------------------------------------------------------
// K2: E[b,i,j] = Q[b,i,:] . hist[b,j,:]  via tcgen05 bf16x3 (NT).
// Tile 128(i) x 256(j), K chunks of 64(d). A = Q hi/lo, B = hist fp32 split.
// ---------------------------------------------------------------------------
__global__ __launch_bounds__(256, 1)
void k2_kernel(const float* __restrict__ Hst, float* __restrict__ out) {
#if TCGEN05_OK
    extern __shared__ char sm[];
    uint32_t sb = smem_u32(sm);
    uint32_t db = (sb + 32 + 1023) & ~1023u;
    char* dp = sm + (db - sb);
    int tid = threadIdx.x, wid = tid >> 5, lane = tid & 31;
    int bb = blockIdx.z;
    int m0 = blockIdx.y * 128;           // i
    int n0 = blockIdx.x * 256;           // j
    const float* Hb = Hst + (size_t)bb * SSEQ * HDIM;
    float* C = out + (size_t)bb * SSTATE * SSEQ;
    size_t arow0 = (size_t)bb * SSTATE + m0;

    if (wid == 0)
        asm volatile("tcgen05.alloc.cta_group::1.sync.aligned.shared::cta.b32 [%0], %1;"
                     :: "r"(sb + 16), "r"(256u) : "memory");
    if (tid == 0) { MBAR_INIT(sb + 0, 1u); MBAR_INIT(sb + 8, 1u); }
    __syncthreads();
    uint32_t td;
    asm volatile("ld.shared.b32 %0, [%1];" : "=r"(td) : "r"(sb + 16));

    int ph0 = 0, ph1 = 0;
    for (int c = 0; c < 8; c++) {
        int buf = c & 1;
        int k0 = c * 64;
        if (c >= 2) {
            if (buf == 0) { MBAR_WAIT(sb + 0, ph0); ph0 ^= 1; }
            else          { MBAR_WAIT(sb + 8, ph1); ph1 ^= 1; }
        }
        char* st = dp + buf * STG_BYTES;
        // A: Q hi/lo bf16.  128 rows x 8 groups = 1024 items per matrix.
#pragma unroll
        for (int t = 0; t < 4; t++) {
            int it = tid + 256 * t;
            int r = it >> 3, g = it & 7;
            int o = SWZ(r * 128 + g * 16);
            size_t src = (arow0 + r) * HDIM + k0 + g * 8;
            *(uint4*)(st + o)            = *(const uint4*)(g_Qhi + src);
            *(uint4*)(st + A_LO_OFF + o) = *(const uint4*)(g_Qlo + src);
        }
        // B: history fp32 -> hi/lo.  256 rows x 8 groups(8 floats) = 2048 items.
#pragma unroll
        for (int t = 0; t < 8; t++) {
            int it = tid + 256 * t;
            int r = it >> 3, g = it & 7;
            const float4* s = (const float4*)(Hb + (size_t)(n0 + r) * HDIM + k0 + g * 8);
            float4 x0 = s[0], x1 = s[1];
            float xs[8] = {x0.x, x0.y, x0.z, x0.w, x1.x, x1.y, x1.z, x1.w};
            union { __nv_bfloat16 b[8]; uint4 u; } Hh, Ll;
#pragma unroll
            for (int e = 0; e < 8; e++) {
                __nv_bfloat16 h = __float2bfloat16(xs[e]);
                Hh.b[e] = h;
                Ll.b[e] = __float2bfloat16(xs[e] - __bfloat162float(h));
            }
            int o = SWZ(r * 128 + g * 16);
            *(uint4*)(st + B_HI_OFF + o) = Hh.u;
            *(uint4*)(st + B_LO_OFF + o) = Ll.u;
        }
        asm volatile("fence.proxy.async.shared::cta;" ::: "memory");
        __syncthreads();
        if (wid == 0 && elect_one()) {
            uint32_t ba = db + buf * STG_BYTES;
            uint64_t ah = make_desc(ba), al = make_desc(ba + A_LO_OFF);
            uint64_t bh = make_desc(ba + B_HI_OFF), bl = make_desc(ba + B_LO_OFF);
#pragma unroll
            for (int ks = 0; ks < 4; ks++)
                mma_ss_f16(td, ah + 2 * ks, bh + 2 * ks, IDESC_128x256,
                           (c == 0 && ks == 0) ? 0u : 1u);
#pragma unroll
            for (int ks = 0; ks < 4; ks++)
                mma_ss_f16(td, ah + 2 * ks, bl + 2 * ks, IDESC_128x256, 1u);
#pragma unroll
            for (int ks = 0; ks < 4; ks++)
                mma_ss_f16(td, al + 2 * ks, bh + 2 * ks, IDESC_128x256, 1u);
            asm volatile(
                "tcgen05.commit.cta_group::1.mbarrier::arrive::one.shared::cluster.b64 [%0];"
                :: "r"(sb + buf * 8) : "memory");
        }
    }
    MBAR_WAIT(sb + 8, ph1);
    asm volatile("tcgen05.fence::after_thread_sync;" ::: "memory");

    // Epilogue: store fp32 energies (bias dropped: softmax is shift-invariant).
    int mloc = ((wid & 3) << 5) + lane;
    int cb = (wid >> 2) * 128;
#pragma unroll
    for (int itn = 0; itn < 4; itn++) {
        uint32_t dr[32];
        LD32X32(dr, td + cb + itn * 32);
        asm volatile("tcgen05.wait::ld.sync.aligned;" ::: "memory");
        float* crow = C + (size_t)(m0 + mloc) * SSEQ + n0 + cb + itn * 32;
#pragma unroll
        for (int g = 0; g < 8; g++) {
            *(float4*)(crow + g * 4) = make_float4(
                __uint_as_float(dr[g * 4 + 0]), __uint_as_float(dr[g * 4 + 1]),
                __uint_as_float(dr[g * 4 + 2]), __uint_as_float(dr[g * 4 + 3]));
        }
    }
    __syncthreads();
    if (wid == 0)
        asm volatile("tcgen05.dealloc.cta_group::1.sync.aligned.b32 %0, %1;"
                     :: "r"(td), "r"(256u));
#endif  // TCGEN05_OK
}

// ---------------------------------------------------------------------------
// K3: in-place softmax over rows of 2048 (unchanged — already 75% of HBM peak)
// ---------------------------------------------------------------------------
__device__ __forceinline__ float fexp_neg(float x) {   // x <= 0
    float t = x * 1.4426950408889634f;
    t = fmaxf(t, -250.0f);
    float fi = t + 12582912.0f;
    int i = __float_as_int(fi) - 0x4B400000;
    float f = t - (fi - 12582912.0f);
    float p = 1.5404e-4f;
    p = fmaf(p, f, 1.33336e-3f);
    p = fmaf(p, f, 9.61813e-3f);
    p = fmaf(p, f, 5.55041e-2f);
    p = fmaf(p, f, 2.40226513e-1f);
    p = fmaf(p, f, 6.93147182e-1f);
    p = fmaf(p, f, 1.0f);
    int i1 = i >> 1;
    int i2 = i - i1;
    float s1 = __int_as_float((i1 + 127) << 23);
    float s2 = __int_as_float((i2 + 127) << 23);
    return p * s1 * s2;
}

__global__ __launch_bounds__(256)
void softmax_kernel(float* __restrict__ data) {
    __shared__ float red[8];
    size_t row = blockIdx.x;
    float4* p = (float4*)(data + row * SSEQ);
    int tid = threadIdx.x;
    int lane = tid & 31, warp = tid >> 5;

    float4 v0 = p[tid];
    float4 v1 = p[tid + 256];
    float m = fmaxf(fmaxf(fmaxf(v0.x, v0.y), fmaxf(v0.z, v0.w)),
                    fmaxf(fmaxf(v1.x, v1.y), fmaxf(v1.z, v1.w)));
#pragma unroll
    for (int off = 16; off; off >>= 1) m = fmaxf(m, __shfl_xor_sync(0xffffffffu, m, off));
    if (lane == 0) red[warp] = m;
    __syncthreads();
    float gm = red[0];
#pragma unroll
    for (int w = 1; w < 8; w++) gm = fmaxf(gm, red[w]);
    __syncthreads();

    float e[8];
    e[0] = fexp_neg(v0.x - gm); e[1] = fexp_neg(v0.y - gm);
    e[2] = fexp_neg(v0.z - gm); e[3] = fexp_neg(v0.w - gm);
    e[4] = fexp_neg(v1.x - gm); e[5] = fexp_neg(v1.y - gm);
    e[6] = fexp_neg(v1.z - gm); e[7] = fexp_neg(v1.w - gm);
    float s = ((e[0] + e[1]) + (e[2] + e[3])) + ((e[4] + e[5]) + (e[6] + e[7]));
#pragma unroll
    for (int off = 16; off; off >>= 1) s += __shfl_xor_sync(0xffffffffu, s, off);
    if (lane == 0) red[warp] = s;
    __syncthreads();
    float gs = ((red[0] + red[1]) + (red[2] + red[3])) +
               ((red[4] + red[5]) + (red[6] + red[7]));
    float inv = 1.0f / gs;

    p[tid]       = make_float4(e[0] * inv, e[1] * inv, e[2] * inv, e[3] * inv);
    p[tid + 256] = make_float4(e[4] * inv, e[5] * inv, e[6] * inv, e[7] * inv);
}

// ---------------------------------------------------------------------------
extern "C" void kernel_launch(void* const* d_in, const int* in_sizes, int n_in,
                              void* d_out, int out_size) {
    (void)in_sizes; (void)n_in; (void)out_size;
    const float* S   = (const float*)d_in[0];  // out_state [64,512,512]
    const float* Hst = (const float*)d_in[1];  // history   [64,2048,512]
    const float* W   = (const float*)d_in[2];  // attn_w    [512,512]
    // d_in[3] (attn_b) intentionally unused: softmax is shift-invariant per row.
    float* out = (float*)d_out;                // [64,512,2048]

    cudaFuncSetAttribute(k1_kernel, cudaFuncAttributeMaxDynamicSharedMemorySize, SMEM_DYN);
    cudaFuncSetAttribute(k2_kernel, cudaFuncAttributeMaxDynamicSharedMemorySize, SMEM_DYN);

    wt_kernel<<<dim3(16, 16), 256>>>(W);
    k1_kernel<<<dim3(HDIM / 256, MTOT / 128), 256, SMEM_DYN>>>(S);       // (2, 256)
    k2_kernel<<<dim3(SSEQ / 256, SSTATE / 128, B_), 256, SMEM_DYN>>>(Hst, out); // (8,4,64)
    softmax_kernel<<<MTOT, 256>>>(out);
}